// round 6
// baseline (speedup 1.0000x reference)
#include <cuda_runtime.h>
#include <cuda_bf16.h>
#include <stdint.h>

// Problem constants (fixed-shape problem)
#define T_ 16
#define N_ 10000
#define F_ 32          // F_IN
#define FH_ 64         // F_H
#define E_ 160000
#define EP_ (E_ + N_)  // edges + self loops
#define R_ (T_ * N_)   // 160000 rows for GEMMs

// ---------------- device scratch (no allocations allowed) ----------------
// Referenced ONLY from device code (host-side reference of __device__ symbols
// was the earlier invalid-address-space trap).
__device__ __align__(256) float g_deg[N_];
__device__ __align__(256) int   g_cnt[N_];
__device__ __align__(256) int   g_rowptr[N_ + 1];
__device__ __align__(256) int   g_cursor[N_];
__device__ __align__(256) int   g_srcs[EP_];
__device__ __align__(256) float g_norm[EP_];
__device__ __align__(256) float g_A1[(size_t)R_ * F_];   // 20MB: S(x), later reused for H@W2
__device__ __align__(256) float g_H [(size_t)R_ * FH_];  // 40MB: hidden layer

// ---------------- init ----------------
__global__ void k_init() {
    int i = blockIdx.x * blockDim.x + threadIdx.x;
    if (i < N_) { g_deg[i] = 0.f; g_cnt[i] = 0; }
}

// ---------------- degree + count histogram ----------------
// edge_index is int32 on device (JAX x64 disabled demotes int64 -> int32).
__global__ void k_degree(const int* __restrict__ ei, const float* __restrict__ ew) {
    int i = blockIdx.x * blockDim.x + threadIdx.x;
    if (i >= EP_) return;
    int d; float w;
    if (i < E_) { d = ei[E_ + i]; w = ew[i]; }     // edge_index[1][e]
    else        { d = i - E_;     w = 1.f;   }     // self loop
    if ((unsigned)d >= N_) return;                 // defensive
    atomicAdd(&g_deg[d], w);
    atomicAdd(&g_cnt[d], 1);
}

// ---------------- single-block exclusive scan over counts ----------------
__global__ void k_scan() {
    __shared__ int warp_sums[32];
    __shared__ int s_carry;
    int tid = threadIdx.x, lane = tid & 31, wid = tid >> 5;
    if (tid == 0) { s_carry = 0; g_rowptr[0] = 0; }
    __syncthreads();
    for (int base = 0; base < N_; base += 1024) {
        int i = base + tid;
        int v = (i < N_) ? g_cnt[i] : 0;
        int x = v;
        #pragma unroll
        for (int o = 1; o < 32; o <<= 1) {
            int y = __shfl_up_sync(0xffffffffu, x, o);
            if (lane >= o) x += y;
        }
        if (lane == 31) warp_sums[wid] = x;
        __syncthreads();
        if (wid == 0) {
            int s = warp_sums[lane];
            #pragma unroll
            for (int o = 1; o < 32; o <<= 1) {
                int y = __shfl_up_sync(0xffffffffu, s, o);
                if (lane >= o) s += y;
            }
            warp_sums[lane] = s;
        }
        __syncthreads();
        int incl = x + (wid > 0 ? warp_sums[wid - 1] : 0) + s_carry;
        if (i < N_) {
            g_rowptr[i + 1] = incl;
            g_cursor[i]     = incl - v;   // exclusive start = write cursor
        }
        __syncthreads();
        if (tid == 1023) s_carry = incl;  // block total (OOB lanes contributed 0)
        __syncthreads();
    }
}

// ---------------- fill CSR buckets with (src, norm) ----------------
__global__ void k_fill(const int* __restrict__ ei, const float* __restrict__ ew) {
    int i = blockIdx.x * blockDim.x + threadIdx.x;
    if (i >= EP_) return;
    int s, d; float w;
    if (i < E_) { s = ei[i]; d = ei[E_ + i]; w = ew[i]; }
    else        { s = i - E_; d = s;         w = 1.f;   }
    if ((unsigned)s >= N_ || (unsigned)d >= N_) return;  // defensive
    float degs = g_deg[s], degd = g_deg[d];
    float ds = (degs > 0.f) ? rsqrtf(degs) : 0.f;
    float dd = (degd > 0.f) ? rsqrtf(degd) : 0.f;
    int pos = atomicAdd(&g_cursor[d], 1);
    g_srcs[pos] = s;
    g_norm[pos] = ds * w * dd;
}

// ---------------- aggregation 1: g_A1[t,n,f] = sum_e norm[e] * x[t,src[e],f] ----------------
// warp per node, lane per feature (F=32), T=16 accumulators per lane (MLP=16 per edge)
__global__ __launch_bounds__(128) void k_agg_in(const float* __restrict__ in) {
    int warp = (blockIdx.x * blockDim.x + threadIdx.x) >> 5;
    int lane = threadIdx.x & 31;
    if (warp >= N_) return;
    int n = warp;
    int beg = g_rowptr[n], end = g_rowptr[n + 1];
    float acc[T_];
    #pragma unroll
    for (int t = 0; t < T_; t++) acc[t] = 0.f;
    const int stride = N_ * F_;
    for (int e = beg; e < end; e++) {
        int   s = g_srcs[e];
        float w = g_norm[e];
        const float* p = in + (size_t)s * F_ + lane;
        #pragma unroll
        for (int t = 0; t < T_; t++)
            acc[t] = fmaf(w, __ldg(p + (size_t)t * stride), acc[t]);
    }
    #pragma unroll
    for (int t = 0; t < T_; t++)
        g_A1[(size_t)t * stride + (size_t)n * F_ + lane] = acc[t];
}

// ---------------- aggregation 2: out[t,n,f] = b2[f] + sum_e norm[e] * g_A1[t,src[e],f] ----------------
__global__ __launch_bounds__(128) void k_agg_out(const float* __restrict__ bias,
                                                 float* __restrict__ out) {
    int warp = (blockIdx.x * blockDim.x + threadIdx.x) >> 5;
    int lane = threadIdx.x & 31;
    if (warp >= N_) return;
    int n = warp;
    int beg = g_rowptr[n], end = g_rowptr[n + 1];
    float acc[T_];
    #pragma unroll
    for (int t = 0; t < T_; t++) acc[t] = 0.f;
    const int stride = N_ * F_;
    for (int e = beg; e < end; e++) {
        int   s = g_srcs[e];
        float w = g_norm[e];
        const float* p = g_A1 + (size_t)s * F_ + lane;
        #pragma unroll
        for (int t = 0; t < T_; t++)
            acc[t] = fmaf(w, p[(size_t)t * stride], acc[t]);
    }
    float b = bias[lane];
    #pragma unroll
    for (int t = 0; t < T_; t++)
        out[(size_t)t * stride + (size_t)n * F_ + lane] = acc[t] + b;
}

// ---------------- GEMM1: g_H = relu(g_A1[R,32] x W1[32,64] + b1) ----------------
__global__ __launch_bounds__(256) void k_gemm1(const float* __restrict__ W,
                                               const float* __restrict__ bias) {
    __shared__ float As[128 * 32];  // 16KB
    __shared__ float Ws[32 * 64];   // 8KB
    int tid = threadIdx.x;
    int r0 = blockIdx.x * 128;
    #pragma unroll
    for (int i = 0; i < 8; i++) Ws[tid + i * 256] = W[tid + i * 256];
    const float4* A4 = (const float4*)(g_A1 + (size_t)r0 * 32);
    float4* As4 = (float4*)As;
    #pragma unroll
    for (int i = 0; i < 4; i++) As4[tid + i * 256] = A4[tid + i * 256];
    __syncthreads();

    int cg = tid & 15;   // 4 output cols: cg*4..cg*4+3
    int rg = tid >> 4;   // 8 rows: rg*8..rg*8+7
    float acc[8][4];
    #pragma unroll
    for (int i = 0; i < 8; i++)
        #pragma unroll
        for (int j = 0; j < 4; j++) acc[i][j] = 0.f;

    #pragma unroll
    for (int k = 0; k < 32; k++) {
        float4 b = ((const float4*)(Ws + k * 64))[cg];
        #pragma unroll
        for (int i = 0; i < 8; i++) {
            float a = As[(rg * 8 + i) * 32 + k];
            acc[i][0] = fmaf(a, b.x, acc[i][0]);
            acc[i][1] = fmaf(a, b.y, acc[i][1]);
            acc[i][2] = fmaf(a, b.z, acc[i][2]);
            acc[i][3] = fmaf(a, b.w, acc[i][3]);
        }
    }
    float4 bb = ((const float4*)bias)[cg];
    #pragma unroll
    for (int i = 0; i < 8; i++) {
        int row = r0 + rg * 8 + i;
        float4 v;
        v.x = fmaxf(acc[i][0] + bb.x, 0.f);
        v.y = fmaxf(acc[i][1] + bb.y, 0.f);
        v.z = fmaxf(acc[i][2] + bb.z, 0.f);
        v.w = fmaxf(acc[i][3] + bb.w, 0.f);
        ((float4*)(g_H + (size_t)row * 64))[cg] = v;
    }
}

// ---------------- GEMM2: g_A1 = g_H[R,64] x W2[64,32] (no bias) ----------------
__global__ __launch_bounds__(256) void k_gemm2(const float* __restrict__ W) {
    __shared__ float As[128 * 64];  // 32KB
    __shared__ float Ws[64 * 32];   // 8KB
    int tid = threadIdx.x;
    int r0 = blockIdx.x * 128;
    #pragma unroll
    for (int i = 0; i < 8; i++) Ws[tid + i * 256] = W[tid + i * 256];
    const float4* A4 = (const float4*)(g_H + (size_t)r0 * 64);
    float4* As4 = (float4*)As;
    #pragma unroll
    for (int i = 0; i < 8; i++) As4[tid + i * 256] = A4[tid + i * 256];
    __syncthreads();

    int cg = tid & 15;   // 2 output cols: cg*2, cg*2+1
    int rg = tid >> 4;   // 8 rows
    float acc[8][2];
    #pragma unroll
    for (int i = 0; i < 8; i++) { acc[i][0] = 0.f; acc[i][1] = 0.f; }

    #pragma unroll
    for (int k = 0; k < 64; k++) {
        float2 b = ((const float2*)(Ws + k * 32))[cg];
        #pragma unroll
        for (int i = 0; i < 8; i++) {
            float a = As[(rg * 8 + i) * 64 + k];
            acc[i][0] = fmaf(a, b.x, acc[i][0]);
            acc[i][1] = fmaf(a, b.y, acc[i][1]);
        }
    }
    #pragma unroll
    for (int i = 0; i < 8; i++) {
        int row = r0 + rg * 8 + i;
        float2 v; v.x = acc[i][0]; v.y = acc[i][1];
        ((float2*)(g_A1 + (size_t)row * 32))[cg] = v;
    }
}

// ---------------- tail zero (if harness output has extra scalar slot) ----------------
__global__ void k_tail(float* __restrict__ out, int start, int total) {
    int i = start + blockIdx.x * blockDim.x + threadIdx.x;
    if (i < total) out[i] = 0.f;
}

// ---------------- launch ----------------
extern "C" void kernel_launch(void* const* d_in, const int* in_sizes, int n_in,
                              void* d_out, int out_size) {
    const float* x  = (const float*)d_in[0];    // (T,N,32) f32
    const int*   ei = (const int*)d_in[1];      // (2,E) int32 (JAX demotes int64)
    const float* ew = (const float*)d_in[2];    // (E,) f32
    // d_in[3] = missing_mask (all false, unused)
    const float* W1 = (const float*)d_in[4];    // (32,64)
    const float* b1 = (const float*)d_in[5];    // (64,)
    const float* W2 = (const float*)d_in[6];    // (64,32)
    const float* b2 = (const float*)d_in[7];    // (32,)
    float* out = (float*)d_out;

    // 1. zero deg/cnt
    k_init<<<(N_ + 255) / 256, 256>>>();
    // 2. degree + count
    k_degree<<<(EP_ + 255) / 256, 256>>>(ei, ew);
    // 3. prefix scan -> rowptr, cursor
    k_scan<<<1, 1024>>>();
    // 4. fill CSR buckets
    k_fill<<<(EP_ + 255) / 256, 256>>>(ei, ew);
    // 5. g_A1 = S(x)   (aggregate on 32 features, before GEMM)
    k_agg_in<<<(N_ * 32 + 127) / 128, 128>>>(x);
    // 6. g_H = relu(g_A1 @ W1 + b1)
    k_gemm1<<<R_ / 128, 256>>>(W1, b1);
    // 7. g_A1 = g_H @ W2
    k_gemm2<<<R_ / 128, 256>>>(W2);
    // 8. out = S(g_A1) + b2
    k_agg_out<<<(N_ * 32 + 127) / 128, 128>>>(b2, out);
    // 9. zero any tail slots (e.g. the trailing scalar "0" in the reference tuple)
    int main_elems = T_ * N_ * F_;
    if (out_size > main_elems) {
        int tail = out_size - main_elems;
        k_tail<<<(tail + 255) / 256, 256>>>(out, main_elems, out_size);
    }
}

// round 7
// speedup vs baseline: 1.1156x; 1.1156x over previous
#include <cuda_runtime.h>
#include <cuda_bf16.h>
#include <stdint.h>

// Problem constants (fixed-shape problem)
#define T_ 16
#define N_ 10000
#define F_ 32          // F_IN
#define FH_ 64         // F_H
#define E_ 160000
#define EP_ (E_ + N_)  // edges + self loops
#define R_ (T_ * N_)   // 160000 rows for GEMMs

// ---------------- device scratch (no allocations allowed) ----------------
// Referenced ONLY from device code.
__device__ __align__(256) float g_deg[N_];
__device__ __align__(256) int   g_cnt[N_];
__device__ __align__(256) int   g_rowptr[N_ + 1];
__device__ __align__(256) int   g_cursor[N_];
__device__ __align__(256) int   g_srcs[EP_];
__device__ __align__(256) float g_norm[EP_];
__device__ __align__(256) float g_A1[(size_t)R_ * F_];   // 20MB: S(x); rewritten in-place to H@W2

// ---------------- f32x2 helpers ----------------
__device__ __forceinline__ void fma2(uint64_t& d, uint64_t a, uint64_t b) {
    asm("fma.rn.f32x2 %0, %1, %2, %0;" : "+l"(d) : "l"(a), "l"(b));
}
__device__ __forceinline__ uint64_t pk(float lo, float hi) {
    uint64_t r; asm("mov.b64 %0, {%1,%2};" : "=l"(r) : "f"(lo), "f"(hi)); return r;
}
__device__ __forceinline__ void upk(uint64_t v, float& lo, float& hi) {
    asm("mov.b64 {%0,%1}, %2;" : "=f"(lo), "=f"(hi) : "l"(v));
}

// ---------------- init ----------------
__global__ void k_init() {
    int i = blockIdx.x * blockDim.x + threadIdx.x;
    if (i < N_) { g_deg[i] = 0.f; g_cnt[i] = 0; }
}

// ---------------- degree + count histogram (edge_index is int32 on device) ----------------
__global__ void k_degree(const int* __restrict__ ei, const float* __restrict__ ew) {
    int i = blockIdx.x * blockDim.x + threadIdx.x;
    if (i >= EP_) return;
    int d; float w;
    if (i < E_) { d = ei[E_ + i]; w = ew[i]; }
    else        { d = i - E_;     w = 1.f;   }
    if ((unsigned)d >= N_) return;
    atomicAdd(&g_deg[d], w);
    atomicAdd(&g_cnt[d], 1);
}

// ---------------- single-block exclusive scan over counts ----------------
__global__ void k_scan() {
    __shared__ int warp_sums[32];
    __shared__ int s_carry;
    int tid = threadIdx.x, lane = tid & 31, wid = tid >> 5;
    if (tid == 0) { s_carry = 0; g_rowptr[0] = 0; }
    __syncthreads();
    for (int base = 0; base < N_; base += 1024) {
        int i = base + tid;
        int v = (i < N_) ? g_cnt[i] : 0;
        int x = v;
        #pragma unroll
        for (int o = 1; o < 32; o <<= 1) {
            int y = __shfl_up_sync(0xffffffffu, x, o);
            if (lane >= o) x += y;
        }
        if (lane == 31) warp_sums[wid] = x;
        __syncthreads();
        if (wid == 0) {
            int s = warp_sums[lane];
            #pragma unroll
            for (int o = 1; o < 32; o <<= 1) {
                int y = __shfl_up_sync(0xffffffffu, s, o);
                if (lane >= o) s += y;
            }
            warp_sums[lane] = s;
        }
        __syncthreads();
        int incl = x + (wid > 0 ? warp_sums[wid - 1] : 0) + s_carry;
        if (i < N_) {
            g_rowptr[i + 1] = incl;
            g_cursor[i]     = incl - v;
        }
        __syncthreads();
        if (tid == 1023) s_carry = incl;
        __syncthreads();
    }
}

// ---------------- fill CSR buckets with (src, norm) ----------------
__global__ void k_fill(const int* __restrict__ ei, const float* __restrict__ ew) {
    int i = blockIdx.x * blockDim.x + threadIdx.x;
    if (i >= EP_) return;
    int s, d; float w;
    if (i < E_) { s = ei[i]; d = ei[E_ + i]; w = ew[i]; }
    else        { s = i - E_; d = s;         w = 1.f;   }
    if ((unsigned)s >= N_ || (unsigned)d >= N_) return;
    float degs = g_deg[s], degd = g_deg[d];
    float ds = (degs > 0.f) ? rsqrtf(degs) : 0.f;
    float dd = (degd > 0.f) ? rsqrtf(degd) : 0.f;
    int pos = atomicAdd(&g_cursor[d], 1);
    g_srcs[pos] = s;
    g_norm[pos] = ds * w * dd;
}

// ---------------- aggregation, float4 lanes ----------------
// warp per node; lane = 8*tg + fq; lane handles t = tg*4+i (i=0..3), features fq*4..fq*4+3
__device__ __forceinline__ float4 fma4(float w, float4 v, float4 a) {
    a.x = fmaf(w, v.x, a.x); a.y = fmaf(w, v.y, a.y);
    a.z = fmaf(w, v.z, a.z); a.w = fmaf(w, v.w, a.w);
    return a;
}

__global__ __launch_bounds__(128) void k_agg_in(const float* __restrict__ in) {
    int warp = (blockIdx.x * blockDim.x + threadIdx.x) >> 5;
    int lane = threadIdx.x & 31;
    if (warp >= N_) return;
    int n = warp, tg = lane >> 3, fq = lane & 7;
    int beg = g_rowptr[n], end = g_rowptr[n + 1];
    const float4* in4 = (const float4*)in;
    const size_t ts = (size_t)N_ * 8;   // float4 stride per t
    float4 acc[4];
    #pragma unroll
    for (int i = 0; i < 4; i++) acc[i] = make_float4(0.f, 0.f, 0.f, 0.f);
    int e = beg;
    for (; e + 1 < end; e += 2) {
        int s0 = g_srcs[e], s1 = g_srcs[e + 1];
        float w0 = g_norm[e], w1 = g_norm[e + 1];
        size_t p0 = (size_t)s0 * 8 + fq, p1 = (size_t)s1 * 8 + fq;
        #pragma unroll
        for (int i = 0; i < 4; i++) {
            int t = tg * 4 + i;
            float4 v0 = __ldg(&in4[(size_t)t * ts + p0]);
            float4 v1 = __ldg(&in4[(size_t)t * ts + p1]);
            acc[i] = fma4(w0, v0, acc[i]);
            acc[i] = fma4(w1, v1, acc[i]);
        }
    }
    if (e < end) {
        int s0 = g_srcs[e]; float w0 = g_norm[e];
        size_t p0 = (size_t)s0 * 8 + fq;
        #pragma unroll
        for (int i = 0; i < 4; i++) {
            int t = tg * 4 + i;
            acc[i] = fma4(w0, __ldg(&in4[(size_t)t * ts + p0]), acc[i]);
        }
    }
    float4* o4 = (float4*)g_A1;
    #pragma unroll
    for (int i = 0; i < 4; i++) {
        int t = tg * 4 + i;
        o4[(size_t)t * ts + (size_t)n * 8 + fq] = acc[i];
    }
}

__global__ __launch_bounds__(128) void k_agg_out(const float* __restrict__ bias,
                                                 float* __restrict__ out) {
    int warp = (blockIdx.x * blockDim.x + threadIdx.x) >> 5;
    int lane = threadIdx.x & 31;
    if (warp >= N_) return;
    int n = warp, tg = lane >> 3, fq = lane & 7;
    int beg = g_rowptr[n], end = g_rowptr[n + 1];
    const float4* in4 = (const float4*)g_A1;
    const size_t ts = (size_t)N_ * 8;
    float4 acc[4];
    #pragma unroll
    for (int i = 0; i < 4; i++) acc[i] = make_float4(0.f, 0.f, 0.f, 0.f);
    int e = beg;
    for (; e + 1 < end; e += 2) {
        int s0 = g_srcs[e], s1 = g_srcs[e + 1];
        float w0 = g_norm[e], w1 = g_norm[e + 1];
        size_t p0 = (size_t)s0 * 8 + fq, p1 = (size_t)s1 * 8 + fq;
        #pragma unroll
        for (int i = 0; i < 4; i++) {
            int t = tg * 4 + i;
            float4 v0 = in4[(size_t)t * ts + p0];
            float4 v1 = in4[(size_t)t * ts + p1];
            acc[i] = fma4(w0, v0, acc[i]);
            acc[i] = fma4(w1, v1, acc[i]);
        }
    }
    if (e < end) {
        int s0 = g_srcs[e]; float w0 = g_norm[e];
        size_t p0 = (size_t)s0 * 8 + fq;
        #pragma unroll
        for (int i = 0; i < 4; i++) {
            int t = tg * 4 + i;
            acc[i] = fma4(w0, in4[(size_t)t * ts + p0], acc[i]);
        }
    }
    float4 b = ((const float4*)bias)[fq];
    float4* o4 = (float4*)out;
    #pragma unroll
    for (int i = 0; i < 4; i++) {
        int t = tg * 4 + i;
        float4 v = acc[i];
        v.x += b.x; v.y += b.y; v.z += b.z; v.w += b.w;
        o4[(size_t)t * ts + (size_t)n * 8 + fq] = v;
    }
}

// ---------------- fused GEMM: g_A1 <- relu(g_A1 @ W1 + b1) @ W2   (in-place, 64-row tiles)
// f32x2 packed FMAs; tiles stored k-major with XOR row-swizzle; W stored duplicated {w,w}.
__global__ __launch_bounds__(128) void k_gemm_fused(const float* __restrict__ W1,
                                                    const float* __restrict__ b1,
                                                    const float* __restrict__ W2) {
    __shared__ float U[4096];    // 16KB union: stage1 As[32][64] / stage2 Wd2[64][64]
    __shared__ float Wd1[4096];  // 16KB: W1 duplicated, [32][128]
    __shared__ float Hs[4096];   // 16KB: H k-major, [64(c)][64(row)], swizzled
    int tid = threadIdx.x;
    int r0 = blockIdx.x * 64;

    // ---- load A tile (transpose to k-major + swizzle) and Wd1 ----
    {
        const float4* A4 = (const float4*)(g_A1 + (size_t)r0 * 32);
        #pragma unroll
        for (int it = 0; it < 4; it++) {
            int idx = it * 128 + tid;       // 0..511
            int row = idx >> 3, c4 = idx & 7;
            float4 v = A4[row * 8 + c4];
            int k0 = c4 * 4;
            U[(k0 + 0) * 64 + (row ^ (((k0 + 0) & 15) * 4))] = v.x;
            U[(k0 + 1) * 64 + (row ^ (((k0 + 1) & 15) * 4))] = v.y;
            U[(k0 + 2) * 64 + (row ^ (((k0 + 2) & 15) * 4))] = v.z;
            U[(k0 + 3) * 64 + (row ^ (((k0 + 3) & 15) * 4))] = v.w;
        }
        #pragma unroll
        for (int it = 0; it < 16; it++) {
            int idx = it * 128 + tid;       // 0..2047
            int k = idx >> 6, c = idx & 63;
            float w = W1[idx];
            Wd1[k * 128 + c * 2] = w;
            Wd1[k * 128 + c * 2 + 1] = w;
        }
    }
    __syncthreads();

    // ---- stage 1: 64x64 = A(64x32) @ W1(32x64); microtile 8 rows x 4 cols ----
    int cg = tid & 15, rg = tid >> 4;
    uint64_t acc[4][4];
    #pragma unroll
    for (int p = 0; p < 4; p++)
        #pragma unroll
        for (int j = 0; j < 4; j++) acc[p][j] = 0ull;

    #pragma unroll
    for (int k = 0; k < 32; k++) {
        int sw = (k & 15) * 4;
        uint64_t a2[4], b2[4];
        #pragma unroll
        for (int p = 0; p < 4; p++)
            a2[p] = *(const uint64_t*)&U[k * 64 + ((rg * 8 + 2 * p) ^ sw)];
        #pragma unroll
        for (int j = 0; j < 4; j++)
            b2[j] = *(const uint64_t*)&Wd1[k * 128 + (cg * 4 + j) * 2];
        #pragma unroll
        for (int p = 0; p < 4; p++)
            #pragma unroll
            for (int j = 0; j < 4; j++)
                fma2(acc[p][j], a2[p], b2[j]);
    }
    __syncthreads();   // all As reads complete before U is overwritten

    // ---- load Wd2 into U, and write H (bias+relu) to Hs k-major ----
    #pragma unroll
    for (int it = 0; it < 16; it++) {
        int idx = it * 128 + tid;           // 0..2047
        int k = idx >> 5, c = idx & 31;
        float w = W2[idx];
        U[k * 64 + c * 2] = w;
        U[k * 64 + c * 2 + 1] = w;
    }
    #pragma unroll
    for (int j = 0; j < 4; j++) {
        int c = cg * 4 + j;
        float bc = b1[c];
        int swc = (c & 15) * 4;
        #pragma unroll
        for (int p = 0; p < 4; p++) {
            float lo, hi; upk(acc[p][j], lo, hi);
            lo = fmaxf(lo + bc, 0.f);
            hi = fmaxf(hi + bc, 0.f);
            *(uint64_t*)&Hs[c * 64 + ((rg * 8 + 2 * p) ^ swc)] = pk(lo, hi);
        }
    }
    __syncthreads();

    // ---- stage 2: 64x32 = H(64x64) @ W2(64x32); microtile 8 rows x 2 cols ----
    int cg2 = tid & 15, rg2 = tid >> 4;
    uint64_t acc2[4][2];
    #pragma unroll
    for (int p = 0; p < 4; p++) { acc2[p][0] = 0ull; acc2[p][1] = 0ull; }

    #pragma unroll
    for (int k = 0; k < 64; k++) {
        int sw = (k & 15) * 4;
        uint64_t a2[4];
        #pragma unroll
        for (int p = 0; p < 4; p++)
            a2[p] = *(const uint64_t*)&Hs[k * 64 + ((rg2 * 8 + 2 * p) ^ sw)];
        uint64_t b20 = *(const uint64_t*)&U[k * 64 + (cg2 * 2) * 2];
        uint64_t b21 = *(const uint64_t*)&U[k * 64 + (cg2 * 2 + 1) * 2];
        #pragma unroll
        for (int p = 0; p < 4; p++) {
            fma2(acc2[p][0], a2[p], b20);
            fma2(acc2[p][1], a2[p], b21);
        }
    }

    // ---- epilogue: write result back in-place (this block's rows only) ----
    #pragma unroll
    for (int p = 0; p < 4; p++) {
        float l0, h0, l1, h1;
        upk(acc2[p][0], l0, h0);
        upk(acc2[p][1], l1, h1);
        int row = r0 + rg2 * 8 + 2 * p;
        *(float2*)&g_A1[(size_t)row * 32 + cg2 * 2]       = make_float2(l0, l1);
        *(float2*)&g_A1[(size_t)(row + 1) * 32 + cg2 * 2] = make_float2(h0, h1);
    }
}

// ---------------- tail zero ----------------
__global__ void k_tail(float* __restrict__ out, int start, int total) {
    int i = start + blockIdx.x * blockDim.x + threadIdx.x;
    if (i < total) out[i] = 0.f;
}

// ---------------- launch ----------------
extern "C" void kernel_launch(void* const* d_in, const int* in_sizes, int n_in,
                              void* d_out, int out_size) {
    const float* x  = (const float*)d_in[0];    // (T,N,32) f32
    const int*   ei = (const int*)d_in[1];      // (2,E) int32
    const float* ew = (const float*)d_in[2];    // (E,) f32
    // d_in[3] = missing_mask (unused)
    const float* W1 = (const float*)d_in[4];    // (32,64)
    const float* b1 = (const float*)d_in[5];    // (64,)
    const float* W2 = (const float*)d_in[6];    // (64,32)
    const float* b2 = (const float*)d_in[7];    // (32,)
    float* out = (float*)d_out;

    k_init<<<(N_ + 255) / 256, 256>>>();
    k_degree<<<(EP_ + 255) / 256, 256>>>(ei, ew);
    k_scan<<<1, 1024>>>();
    k_fill<<<(EP_ + 255) / 256, 256>>>(ei, ew);
    // g_A1 = S(x)
    k_agg_in<<<(N_ + 3) / 4, 128>>>(x);
    // g_A1 = relu(g_A1 @ W1 + b1) @ W2   (fused, in-place)
    k_gemm_fused<<<R_ / 64, 128>>>(W1, b1, W2);
    // out = S(g_A1) + b2
    k_agg_out<<<(N_ + 3) / 4, 128>>>(b2, out);
    int main_elems = T_ * N_ * F_;
    if (out_size > main_elems) {
        int tail = out_size - main_elems;
        k_tail<<<(tail + 255) / 256, 256>>>(out, main_elems, out_size);
    }
}

// round 8
// speedup vs baseline: 1.2915x; 1.1577x over previous
#include <cuda_runtime.h>
#include <cuda_bf16.h>
#include <stdint.h>

// Problem constants (fixed-shape problem)
#define T_ 16
#define N_ 10000
#define F_ 32          // F_IN
#define FH_ 64         // F_H
#define E_ 160000
#define EP_ (E_ + N_)  // edges + self loops
#define R_ (T_ * N_)   // 160000 rows for GEMMs

// ---------------- device scratch (no allocations allowed) ----------------
__device__ __align__(256) float g_deg[N_];
__device__ __align__(256) int   g_cnt[N_];
__device__ __align__(256) int   g_rowptr[N_ + 1];
__device__ __align__(256) int   g_cursor[N_];
__device__ __align__(256) int   g_srcs[EP_];
__device__ __align__(256) float g_norm[EP_];
__device__ __align__(256) float g_A1[(size_t)R_ * F_];   // 20MB: S(x); rewritten in-place to H@W2

// ---------------- f32x2 helpers ----------------
__device__ __forceinline__ void fma2(uint64_t& d, uint64_t a, uint64_t b) {
    asm("fma.rn.f32x2 %0, %1, %2, %0;" : "+l"(d) : "l"(a), "l"(b));
}
__device__ __forceinline__ uint64_t pk(float lo, float hi) {
    uint64_t r; asm("mov.b64 %0, {%1,%2};" : "=l"(r) : "f"(lo), "f"(hi)); return r;
}
__device__ __forceinline__ void upk(uint64_t v, float& lo, float& hi) {
    asm("mov.b64 {%0,%1}, %2;" : "=f"(lo), "=f"(hi) : "l"(v));
}

// ---------------- init ----------------
__global__ void k_init() {
    int i = blockIdx.x * blockDim.x + threadIdx.x;
    if (i < N_) { g_deg[i] = 0.f; g_cnt[i] = 0; }
}

// ---------------- degree + count histogram, 4 edges/thread ----------------
#define NV_ (E_ / 4)     // 40000 vector-edge threads
#define NSL_ (N_ / 4)    // 2500 self-loop threads
__global__ void k_degree(const int* __restrict__ ei, const float* __restrict__ ew) {
    int i = blockIdx.x * blockDim.x + threadIdx.x;
    if (i < NV_) {
        int4   d4 = ((const int4*)(ei + E_))[i];
        float4 w4 = ((const float4*)ew)[i];
        if ((unsigned)d4.x < N_) { atomicAdd(&g_deg[d4.x], w4.x); atomicAdd(&g_cnt[d4.x], 1); }
        if ((unsigned)d4.y < N_) { atomicAdd(&g_deg[d4.y], w4.y); atomicAdd(&g_cnt[d4.y], 1); }
        if ((unsigned)d4.z < N_) { atomicAdd(&g_deg[d4.z], w4.z); atomicAdd(&g_cnt[d4.z], 1); }
        if ((unsigned)d4.w < N_) { atomicAdd(&g_deg[d4.w], w4.w); atomicAdd(&g_cnt[d4.w], 1); }
    } else {
        int j = i - NV_;
        if (j < NSL_) {
            int base = j * 4;
            #pragma unroll
            for (int r = 0; r < 4; r++) {
                atomicAdd(&g_deg[base + r], 1.f);
                atomicAdd(&g_cnt[base + r], 1);
            }
        }
    }
}

// ---------------- single-block exclusive scan over counts ----------------
__global__ void k_scan() {
    __shared__ int warp_sums[32];
    __shared__ int s_carry;
    int tid = threadIdx.x, lane = tid & 31, wid = tid >> 5;
    if (tid == 0) { s_carry = 0; g_rowptr[0] = 0; }
    __syncthreads();
    for (int base = 0; base < N_; base += 1024) {
        int i = base + tid;
        int v = (i < N_) ? g_cnt[i] : 0;
        int x = v;
        #pragma unroll
        for (int o = 1; o < 32; o <<= 1) {
            int y = __shfl_up_sync(0xffffffffu, x, o);
            if (lane >= o) x += y;
        }
        if (lane == 31) warp_sums[wid] = x;
        __syncthreads();
        if (wid == 0) {
            int s = warp_sums[lane];
            #pragma unroll
            for (int o = 1; o < 32; o <<= 1) {
                int y = __shfl_up_sync(0xffffffffu, s, o);
                if (lane >= o) s += y;
            }
            warp_sums[lane] = s;
        }
        __syncthreads();
        int incl = x + (wid > 0 ? warp_sums[wid - 1] : 0) + s_carry;
        if (i < N_) {
            g_rowptr[i + 1] = incl;
            g_cursor[i]     = incl - v;
        }
        __syncthreads();
        if (tid == 1023) s_carry = incl;
        __syncthreads();
    }
}

// ---------------- fill CSR buckets with (src, norm), 4 edges/thread ----------------
__device__ __forceinline__ void fill_one(int s, int d, float w) {
    if ((unsigned)s >= N_ || (unsigned)d >= N_) return;
    float degs = g_deg[s], degd = g_deg[d];
    float ds = (degs > 0.f) ? rsqrtf(degs) : 0.f;
    float dd = (degd > 0.f) ? rsqrtf(degd) : 0.f;
    int pos = atomicAdd(&g_cursor[d], 1);
    g_srcs[pos] = s;
    g_norm[pos] = ds * w * dd;
}
__global__ void k_fill(const int* __restrict__ ei, const float* __restrict__ ew) {
    int i = blockIdx.x * blockDim.x + threadIdx.x;
    if (i < NV_) {
        int4   s4 = ((const int4*)ei)[i];
        int4   d4 = ((const int4*)(ei + E_))[i];
        float4 w4 = ((const float4*)ew)[i];
        fill_one(s4.x, d4.x, w4.x);
        fill_one(s4.y, d4.y, w4.y);
        fill_one(s4.z, d4.z, w4.z);
        fill_one(s4.w, d4.w, w4.w);
    } else {
        int j = i - NV_;
        if (j < NSL_) {
            int base = j * 4;
            #pragma unroll
            for (int r = 0; r < 4; r++) fill_one(base + r, base + r, 1.f);
        }
    }
}

// ---------------- aggregation, float4 lanes ----------------
__device__ __forceinline__ float4 fma4(float w, float4 v, float4 a) {
    a.x = fmaf(w, v.x, a.x); a.y = fmaf(w, v.y, a.y);
    a.z = fmaf(w, v.z, a.z); a.w = fmaf(w, v.w, a.w);
    return a;
}

__global__ __launch_bounds__(128) void k_agg_in(const float* __restrict__ in) {
    int warp = (blockIdx.x * blockDim.x + threadIdx.x) >> 5;
    int lane = threadIdx.x & 31;
    if (warp >= N_) return;
    int n = warp, tg = lane >> 3, fq = lane & 7;
    int beg = g_rowptr[n], end = g_rowptr[n + 1];
    const float4* in4 = (const float4*)in;
    const size_t ts = (size_t)N_ * 8;
    float4 acc[4];
    #pragma unroll
    for (int i = 0; i < 4; i++) acc[i] = make_float4(0.f, 0.f, 0.f, 0.f);
    int e = beg;
    for (; e + 1 < end; e += 2) {
        int s0 = g_srcs[e], s1 = g_srcs[e + 1];
        float w0 = g_norm[e], w1 = g_norm[e + 1];
        size_t p0 = (size_t)s0 * 8 + fq, p1 = (size_t)s1 * 8 + fq;
        #pragma unroll
        for (int i = 0; i < 4; i++) {
            int t = tg * 4 + i;
            float4 v0 = __ldg(&in4[(size_t)t * ts + p0]);
            float4 v1 = __ldg(&in4[(size_t)t * ts + p1]);
            acc[i] = fma4(w0, v0, acc[i]);
            acc[i] = fma4(w1, v1, acc[i]);
        }
    }
    if (e < end) {
        int s0 = g_srcs[e]; float w0 = g_norm[e];
        size_t p0 = (size_t)s0 * 8 + fq;
        #pragma unroll
        for (int i = 0; i < 4; i++) {
            int t = tg * 4 + i;
            acc[i] = fma4(w0, __ldg(&in4[(size_t)t * ts + p0]), acc[i]);
        }
    }
    float4* o4 = (float4*)g_A1;
    #pragma unroll
    for (int i = 0; i < 4; i++) {
        int t = tg * 4 + i;
        o4[(size_t)t * ts + (size_t)n * 8 + fq] = acc[i];
    }
}

__global__ __launch_bounds__(128) void k_agg_out(const float* __restrict__ bias,
                                                 float* __restrict__ out) {
    int warp = (blockIdx.x * blockDim.x + threadIdx.x) >> 5;
    int lane = threadIdx.x & 31;
    if (warp >= N_) return;
    int n = warp, tg = lane >> 3, fq = lane & 7;
    int beg = g_rowptr[n], end = g_rowptr[n + 1];
    const float4* in4 = (const float4*)g_A1;
    const size_t ts = (size_t)N_ * 8;
    float4 acc[4];
    #pragma unroll
    for (int i = 0; i < 4; i++) acc[i] = make_float4(0.f, 0.f, 0.f, 0.f);
    int e = beg;
    for (; e + 1 < end; e += 2) {
        int s0 = g_srcs[e], s1 = g_srcs[e + 1];
        float w0 = g_norm[e], w1 = g_norm[e + 1];
        size_t p0 = (size_t)s0 * 8 + fq, p1 = (size_t)s1 * 8 + fq;
        #pragma unroll
        for (int i = 0; i < 4; i++) {
            int t = tg * 4 + i;
            float4 v0 = in4[(size_t)t * ts + p0];
            float4 v1 = in4[(size_t)t * ts + p1];
            acc[i] = fma4(w0, v0, acc[i]);
            acc[i] = fma4(w1, v1, acc[i]);
        }
    }
    if (e < end) {
        int s0 = g_srcs[e]; float w0 = g_norm[e];
        size_t p0 = (size_t)s0 * 8 + fq;
        #pragma unroll
        for (int i = 0; i < 4; i++) {
            int t = tg * 4 + i;
            acc[i] = fma4(w0, in4[(size_t)t * ts + p0], acc[i]);
        }
    }
    float4 b = ((const float4*)bias)[fq];
    float4* o4 = (float4*)out;
    #pragma unroll
    for (int i = 0; i < 4; i++) {
        int t = tg * 4 + i;
        float4 v = acc[i];
        v.x += b.x; v.y += b.y; v.z += b.z; v.w += b.w;
        o4[(size_t)t * ts + (size_t)n * 8 + fq] = v;
    }
}

// ---------------- fused GEMM: g_A1 <- relu(g_A1 @ W1 + b1) @ W2  (in-place, 128-row tiles)
// 128 threads; thread tile 8 rows x 8 cols (stage1) / 8 rows x 4 cols (stage2).
// f32x2 packed FMAs; A/H tiles k-major with XOR row-swizzle; W duplicated {w,w}, jj-interleaved.
__global__ __launch_bounds__(128) void k_gemm_fused(const float* __restrict__ W1,
                                                    const float* __restrict__ b1,
                                                    const float* __restrict__ W2) {
    __shared__ float S[12288];     // 48KB
    float* U   = S;                // [0,4096):  stage1 As k-major; stage2 Wd2
    float* Wd1 = S + 4096;         // [4096,8192): W1 dup (stage1 only)
    float* Hs  = S + 4096;         // [4096,12288): H k-major (after stage1)
    int tid = threadIdx.x;
    int r0 = blockIdx.x * 128;

    // ---- phase 1: load A tile (transpose to k-major, swizzled) + Wd1 ----
    {
        const float4* A4 = (const float4*)(g_A1 + (size_t)r0 * 32);
        #pragma unroll
        for (int it = 0; it < 8; it++) {
            int idx = it * 128 + tid;      // 0..1023
            int row = idx >> 3, c4 = idx & 7;
            float4 v = A4[idx];
            int k0 = c4 * 4;
            int sw = c4 * 4;               // sigmaA(k) = (k>>2)*4
            U[(k0 + 0) * 128 + (row ^ sw)] = v.x;
            U[(k0 + 1) * 128 + (row ^ sw)] = v.y;
            U[(k0 + 2) * 128 + (row ^ sw)] = v.z;
            U[(k0 + 3) * 128 + (row ^ sw)] = v.w;
        }
        // Wd1: pair for (k,c) at k*128 + (c&7)*16 + (c>>3)*2
        #pragma unroll
        for (int it = 0; it < 16; it++) {
            int idx = it * 128 + tid;      // 0..2047
            int k = idx >> 6, c = idx & 63;
            float w = W1[idx];
            int off = k * 128 + (c & 7) * 16 + (c >> 3) * 2;
            Wd1[off] = w; Wd1[off + 1] = w;
        }
    }
    __syncthreads();

    // ---- stage 1: H(128x64) = A(128x32) @ W1(32x64) ----
    int rg = tid >> 3, cg = tid & 7;       // rows rg*8..+7, cols cg*8..+7
    uint64_t acc[4][8];
    #pragma unroll
    for (int p = 0; p < 4; p++)
        #pragma unroll
        for (int j = 0; j < 8; j++) acc[p][j] = 0ull;

    #pragma unroll
    for (int k = 0; k < 32; k++) {
        int sw = (k >> 2) * 4;
        uint64_t a2[4], b2[8];
        #pragma unroll
        for (int p = 0; p < 4; p++)
            a2[p] = *(const uint64_t*)&U[k * 128 + ((rg * 8 + 2 * p) ^ sw)];
        #pragma unroll
        for (int j = 0; j < 8; j++)
            b2[j] = *(const uint64_t*)&Wd1[k * 128 + j * 16 + cg * 2];
        #pragma unroll
        for (int p = 0; p < 4; p++)
            #pragma unroll
            for (int j = 0; j < 8; j++)
                fma2(acc[p][j], a2[p], b2[j]);
    }
    __syncthreads();   // U + Wd1 dead

    // ---- phase 3: load Wd2 into U; write H (bias+relu) to Hs ----
    // Wd2: pair for (k,c) at k*64 + (c&3)*16 + (c>>2)*2
    #pragma unroll
    for (int it = 0; it < 16; it++) {
        int idx = it * 128 + tid;          // 0..2047
        int k = idx >> 5, c = idx & 31;
        float w = W2[idx];
        int off = k * 64 + (c & 3) * 16 + (c >> 2) * 2;
        U[off] = w; U[off + 1] = w;
    }
    {
        int q = cg;                        // c>>3 for c = cg*8+j
        int sh = (q & 3) * 4 + (q >> 2) * 2;  // sigmaH(c)
        #pragma unroll
        for (int j = 0; j < 8; j++) {
            int c = cg * 8 + j;
            float bc = b1[c];
            #pragma unroll
            for (int p = 0; p < 4; p++) {
                float lo, hi; upk(acc[p][j], lo, hi);
                lo = fmaxf(lo + bc, 0.f);
                hi = fmaxf(hi + bc, 0.f);
                *(uint64_t*)&Hs[c * 128 + ((rg * 8 + 2 * p) ^ sh)] = pk(lo, hi);
            }
        }
    }
    __syncthreads();

    // ---- stage 2: Out(128x32) = H(128x64) @ W2(64x32) ----
    uint64_t acc2[4][4];
    #pragma unroll
    for (int p = 0; p < 4; p++)
        #pragma unroll
        for (int j = 0; j < 4; j++) acc2[p][j] = 0ull;

    #pragma unroll
    for (int k = 0; k < 64; k++) {
        int q = k >> 3;
        int sh = (q & 3) * 4 + (q >> 2) * 2;
        uint64_t a2[4], b2[4];
        #pragma unroll
        for (int p = 0; p < 4; p++)
            a2[p] = *(const uint64_t*)&Hs[k * 128 + ((rg * 8 + 2 * p) ^ sh)];
        #pragma unroll
        for (int j = 0; j < 4; j++)
            b2[j] = *(const uint64_t*)&U[k * 64 + j * 16 + cg * 2];
        #pragma unroll
        for (int p = 0; p < 4; p++)
            #pragma unroll
            for (int j = 0; j < 4; j++)
                fma2(acc2[p][j], a2[p], b2[j]);
    }

    // ---- epilogue: write back in-place (cols cg*4..cg*4+3, rows rg*8..+7) ----
    #pragma unroll
    for (int p = 0; p < 4; p++) {
        float lo0, hi0, lo1, hi1, lo2, hi2, lo3, hi3;
        upk(acc2[p][0], lo0, hi0);
        upk(acc2[p][1], lo1, hi1);
        upk(acc2[p][2], lo2, hi2);
        upk(acc2[p][3], lo3, hi3);
        int row = r0 + rg * 8 + 2 * p;
        *(float4*)&g_A1[(size_t)row * 32 + cg * 4]       = make_float4(lo0, lo1, lo2, lo3);
        *(float4*)&g_A1[(size_t)(row + 1) * 32 + cg * 4] = make_float4(hi0, hi1, hi2, hi3);
    }
}

// ---------------- tail zero ----------------
__global__ void k_tail(float* __restrict__ out, int start, int total) {
    int i = start + blockIdx.x * blockDim.x + threadIdx.x;
    if (i < total) out[i] = 0.f;
}

// ---------------- launch ----------------
extern "C" void kernel_launch(void* const* d_in, const int* in_sizes, int n_in,
                              void* d_out, int out_size) {
    const float* x  = (const float*)d_in[0];    // (T,N,32) f32
    const int*   ei = (const int*)d_in[1];      // (2,E) int32
    const float* ew = (const float*)d_in[2];    // (E,) f32
    // d_in[3] = missing_mask (unused)
    const float* W1 = (const float*)d_in[4];    // (32,64)
    const float* b1 = (const float*)d_in[5];    // (64,)
    const float* W2 = (const float*)d_in[6];    // (64,32)
    const float* b2 = (const float*)d_in[7];    // (32,)
    float* out = (float*)d_out;

    k_init<<<(N_ + 255) / 256, 256>>>();
    k_degree<<<(NV_ + NSL_ + 255) / 256, 256>>>(ei, ew);
    k_scan<<<1, 1024>>>();
    k_fill<<<(NV_ + NSL_ + 255) / 256, 256>>>(ei, ew);
    // g_A1 = S(x)
    k_agg_in<<<(N_ + 3) / 4, 128>>>(x);
    // g_A1 = relu(g_A1 @ W1 + b1) @ W2   (fused, in-place)
    k_gemm_fused<<<R_ / 128, 128>>>(W1, b1, W2);
    // out = S(g_A1) + b2
    k_agg_out<<<(N_ + 3) / 4, 128>>>(b2, out);
    int main_elems = T_ * N_ * F_;
    if (out_size > main_elems) {
        int tail = out_size - main_elems;
        k_tail<<<(tail + 255) / 256, 256>>>(out, main_elems, out_size);
    }
}